// round 5
// baseline (speedup 1.0000x reference)
#include <cuda_runtime.h>
#include <math.h>
#include <stdint.h>

#define B_  8
#define Q_  512
#define D_  4096
#define H_  1024

#define STAGES  4
#define TM_     128
#define TN_     256
#define BK      16
#define STRD    20                       // K-major smem row stride (floats)
#define STRD_BN 264                      // NN B smem row stride (floats)
#define A_FLOATS (TM_ * STRD)            // 2560
#define B_FLOATS (TN_ * STRD)            // 5120 (>= 16*264 = 4224)
#define STAGE_FLOATS (A_FLOATS + B_FLOATS)   // 7680
#define SMEM_BYTES (STAGES * STAGE_FLOATS * 4)  // 122880

// ---------------- scratch (static device memory; no allocs allowed) ----------
__device__ float g_q[(size_t)B_ * Q_ * H_];       // projected queries, tf32
__device__ float g_doc[(size_t)B_ * D_ * H_];     // tf32(doc)
__device__ float g_W[(size_t)H_ * H_];            // tf32(W)

// ---------------- helpers -----------------------------------------------------
__device__ __forceinline__ float tf32_rn(float x) {
    float r; asm("cvt.rna.tf32.f32 %0, %1;" : "=f"(r) : "f"(x)); return r;
}
__device__ __forceinline__ uint32_t tf32u(float x) {
    float r; asm("cvt.rna.tf32.f32 %0, %1;" : "=f"(r) : "f"(x));
    return __float_as_uint(r);
}
__device__ __forceinline__ void cp_async16(uint32_t dst, const void* src) {
    asm volatile("cp.async.cg.shared.global [%0], [%1], 16;" :: "r"(dst), "l"(src));
}
#define CP_COMMIT() asm volatile("cp.async.commit_group;" ::: "memory")
#define CP_WAIT(n)  asm volatile("cp.async.wait_group %0;" :: "n"(n) : "memory")

__device__ __forceinline__ uint32_t smem_u32(const void* p) {
    uint32_t a;
    asm("{ .reg .u64 t; cvta.to.shared.u64 t, %1; cvt.u32.u64 %0, t; }" : "=r"(a) : "l"(p));
    return a;
}

__device__ __forceinline__ void mma_tf32(float* c, const uint32_t* a, const uint32_t* b) {
    asm volatile(
        "mma.sync.aligned.m16n8k8.row.col.f32.tf32.tf32.f32 "
        "{%0,%1,%2,%3}, {%4,%5,%6,%7}, {%8,%9}, {%0,%1,%2,%3};"
        : "+f"(c[0]), "+f"(c[1]), "+f"(c[2]), "+f"(c[3])
        : "r"(a[0]), "r"(a[1]), "r"(a[2]), "r"(a[3]), "r"(b[0]), "r"(b[1]));
}

// ---------------- warp-MMA TF32 GEMM (CTA 128x256, warp 64x64) ----------------
// C[m][n] = alpha * sum_k A[m][k] * op(B) (+ bias[n])
//   A: [M,K] K-major, pitch lda (fp32; CVT_A => round in-register)
//   B_KMAJOR=1: B is [N,K] K-major rows, pitch ldb (must be pre-rounded tf32)
//   B_KMAJOR=0: B is [K,N], pitch ldb (must be pre-rounded tf32)
// grid: (N/256, M/128, batches), 256 threads.
template <bool B_KMAJOR, bool HAS_BIAS, bool CVT_A, bool CVT_OUT>
__global__ void __launch_bounds__(256, 1) wgemm(
    const float* __restrict__ A, const float* __restrict__ Bm,
    float* __restrict__ C, const float* __restrict__ bias,
    int K, int lda, int ldb, int ldc, float alpha,
    size_t strideA, size_t strideB, size_t strideC)
{
    extern __shared__ float smf[];
    const uint32_t sbase = smem_u32(smf);

    const int tid  = threadIdx.x;
    const int lane = tid & 31;
    const int wid  = tid >> 5;
    const int row  = lane >> 2;          // 0..7
    const int tig  = lane & 3;           // 0..3
    const int warp_m = (wid & 1) * 64;   // 2 warps in M
    const int warp_n = (wid >> 1) * 64;  // 4 warps in N

    const size_t batch = blockIdx.z;
    const float* Ab = A + batch * strideA + (size_t)(blockIdx.y * TM_) * lda;
    const float* Bb;
    if (B_KMAJOR)
        Bb = Bm + batch * strideB + (size_t)(blockIdx.x * TN_) * ldb;
    else
        Bb = Bm + batch * strideB + blockIdx.x * TN_;

    float acc[4][8][4];
#pragma unroll
    for (int mt = 0; mt < 4; mt++)
#pragma unroll
        for (int nt = 0; nt < 8; nt++)
#pragma unroll
            for (int i = 0; i < 4; i++) acc[mt][nt][i] = 0.0f;

    const int NK = K / BK;

    auto load_stage = [&](int kb) {
        const int s = kb % STAGES;
        const uint32_t stA = sbase + s * STAGE_FLOATS * 4;
        const uint32_t stB = stA + A_FLOATS * 4;
        const float* gA = Ab + kb * BK;
#pragma unroll
        for (int r = 0; r < 2; r++) {
            const int c = tid + r * 256;          // 0..511
            const int ar = c >> 2, aq = c & 3;
            cp_async16(stA + (ar * STRD + aq * 4) * 4, gA + (size_t)ar * lda + aq * 4);
        }
        if (B_KMAJOR) {
            const float* gB = Bb + kb * BK;
#pragma unroll
            for (int r = 0; r < 4; r++) {
                const int c = tid + r * 256;      // 0..1023
                const int br = c >> 2, bq = c & 3;
                cp_async16(stB + (br * STRD + bq * 4) * 4, gB + (size_t)br * ldb + bq * 4);
            }
        } else {
            const float* gB = Bb + (size_t)(kb * BK) * ldb;
#pragma unroll
            for (int r = 0; r < 4; r++) {
                const int c = tid + r * 256;      // 0..1023
                const int bk = c >> 6, bn = (c & 63) * 4;
                cp_async16(stB + (bk * STRD_BN + bn) * 4, gB + (size_t)bk * ldb + bn);
            }
        }
    };

#pragma unroll
    for (int s = 0; s < STAGES - 1; s++) {
        load_stage(s);
        CP_COMMIT();
    }

    for (int kb = 0; kb < NK; kb++) {
        CP_WAIT(STAGES - 2);
        __syncthreads();

        const int kn = kb + STAGES - 1;
        if (kn < NK) load_stage(kn);
        CP_COMMIT();

        const float* As = smf + (kb % STAGES) * STAGE_FLOATS;
        const float* Bs = As + A_FLOATS;
#pragma unroll
        for (int kk = 0; kk < BK; kk += 8) {
            uint32_t a[4][4], b[8][2];
#pragma unroll
            for (int mt = 0; mt < 4; mt++) {
                const float* ap = As + (warp_m + mt * 16 + row) * STRD + kk + tig;
                if (CVT_A) {
                    a[mt][0] = tf32u(ap[0]);
                    a[mt][1] = tf32u(ap[8 * STRD]);
                    a[mt][2] = tf32u(ap[4]);
                    a[mt][3] = tf32u(ap[8 * STRD + 4]);
                } else {
                    a[mt][0] = __float_as_uint(ap[0]);
                    a[mt][1] = __float_as_uint(ap[8 * STRD]);
                    a[mt][2] = __float_as_uint(ap[4]);
                    a[mt][3] = __float_as_uint(ap[8 * STRD + 4]);
                }
            }
#pragma unroll
            for (int nt = 0; nt < 8; nt++) {
                if (B_KMAJOR) {
                    const float* bp = Bs + (warp_n + nt * 8 + row) * STRD + kk + tig;
                    b[nt][0] = __float_as_uint(bp[0]);
                    b[nt][1] = __float_as_uint(bp[4]);
                } else {
                    const float* bp = Bs + (size_t)(kk + tig) * STRD_BN + warp_n + nt * 8 + row;
                    b[nt][0] = __float_as_uint(bp[0]);
                    b[nt][1] = __float_as_uint(bp[4 * STRD_BN]);
                }
            }
#pragma unroll
            for (int mt = 0; mt < 4; mt++)
#pragma unroll
                for (int nt = 0; nt < 8; nt++)
                    mma_tf32(acc[mt][nt], a[mt], b[nt]);
        }
        __syncthreads();
    }

    // ---- epilogue ----
    float* Cb = C + batch * strideC;
#pragma unroll
    for (int mt = 0; mt < 4; mt++) {
        const int r0 = blockIdx.y * TM_ + warp_m + mt * 16 + row;
#pragma unroll
        for (int nt = 0; nt < 8; nt++) {
            const int col = blockIdx.x * TN_ + warp_n + nt * 8 + 2 * tig;
            float bx = 0.f, by = 0.f;
            if (HAS_BIAS) { bx = __ldg(bias + col); by = __ldg(bias + col + 1); }
            float2 v0, v1;
            v0.x = acc[mt][nt][0] * alpha + bx;
            v0.y = acc[mt][nt][1] * alpha + by;
            v1.x = acc[mt][nt][2] * alpha + bx;
            v1.y = acc[mt][nt][3] * alpha + by;
            if (CVT_OUT) {
                v0.x = tf32_rn(v0.x); v0.y = tf32_rn(v0.y);
                v1.x = tf32_rn(v1.x); v1.y = tf32_rn(v1.y);
            }
            *(float2*)(Cb + (size_t)r0 * ldc + col) = v0;
            *(float2*)(Cb + (size_t)(r0 + 8) * ldc + col) = v1;
        }
    }
}

// ---------------- elementwise tf32 round copy ---------------------------------
__global__ void k_cvt(const float* __restrict__ src, float* __restrict__ dst) {
    size_t i = (size_t)blockIdx.x * blockDim.x + threadIdx.x;
    float4 v = ((const float4*)src)[i];
    v.x = tf32_rn(v.x); v.y = tf32_rn(v.y); v.z = tf32_rn(v.z); v.w = tf32_rn(v.w);
    ((float4*)dst)[i] = v;
}

// ---------------- masked softmax over D (in place) ----------------------------
__global__ void __launch_bounds__(256) softmax_kernel(
    float* __restrict__ attn, const int* __restrict__ mask)
{
    const int row = blockIdx.x;            // b*Q_ + q
    const int b = row / Q_;
    const int* mrow = mask + (size_t)b * D_;
    float* s = attn + (size_t)row * D_;
    const int tid = threadIdx.x;

    float v[16];
    int mk[16];
    float mx = -INFINITY;
#pragma unroll
    for (int i = 0; i < 16; i++) {
        int d = tid + i * 256;
        mk[i] = mrow[d];
        float x = s[d];
        v[i] = (mk[i] != 0) ? x : -INFINITY;
        mx = fmaxf(mx, v[i]);
    }

    __shared__ float red[8];
#pragma unroll
    for (int off = 16; off > 0; off >>= 1)
        mx = fmaxf(mx, __shfl_xor_sync(0xffffffffu, mx, off));
    if ((tid & 31) == 0) red[tid >> 5] = mx;
    __syncthreads();
    if (tid < 32) {
        float m2 = (tid < 8) ? red[tid] : -INFINITY;
#pragma unroll
        for (int off = 4; off > 0; off >>= 1)
            m2 = fmaxf(m2, __shfl_xor_sync(0xffffffffu, m2, off));
        if (tid == 0) red[0] = m2;
    }
    __syncthreads();
    mx = red[0];

    float sum = 0.0f;
#pragma unroll
    for (int i = 0; i < 16; i++) {
        float e = (mk[i] != 0) ? expf(v[i] - mx) : 0.0f;
        v[i] = e;
        sum += e;
    }
#pragma unroll
    for (int off = 16; off > 0; off >>= 1)
        sum += __shfl_xor_sync(0xffffffffu, sum, off);
    __syncthreads();
    if ((tid & 31) == 0) red[tid >> 5] = sum;
    __syncthreads();
    if (tid < 32) {
        float s2 = (tid < 8) ? red[tid] : 0.0f;
#pragma unroll
        for (int off = 4; off > 0; off >>= 1)
            s2 += __shfl_xor_sync(0xffffffffu, s2, off);
        if (tid == 0) red[0] = s2;
    }
    __syncthreads();
    const float inv = 1.0f / red[0];

#pragma unroll
    for (int i = 0; i < 16; i++) {
        int d = tid + i * 256;
        s[d] = v[i] * inv;
    }
}

// ---------------- launch --------------------------------------------------------
extern "C" void kernel_launch(void* const* d_in, const int* in_sizes, int n_in,
                              void* d_out, int out_size)
{
    const float* query = (const float*)d_in[0];   // [B,Q,H]
    const float* doc   = (const float*)d_in[1];   // [B,D,H]
    const int*   mask  = (const int*)d_in[2];     // [B,D]
    const float* W     = (const float*)d_in[3];   // [H,H]
    const float* bias  = (const float*)d_in[4];   // [H]

    float* out = (float*)d_out;
    float* retrieved = out;                               // [B,Q,H]
    float* attn = out + (size_t)B_ * Q_ * H_;             // [B,Q,D]

    float *p_q, *p_doc, *p_W;
    cudaGetSymbolAddress((void**)&p_q, g_q);
    cudaGetSymbolAddress((void**)&p_doc, g_doc);
    cudaGetSymbolAddress((void**)&p_W, g_W);

    cudaFuncSetAttribute(wgemm<false, true, true, true>,
                         cudaFuncAttributeMaxDynamicSharedMemorySize, SMEM_BYTES);
    cudaFuncSetAttribute(wgemm<true, false, false, false>,
                         cudaFuncAttributeMaxDynamicSharedMemorySize, SMEM_BYTES);
    cudaFuncSetAttribute(wgemm<false, false, true, false>,
                         cudaFuncAttributeMaxDynamicSharedMemorySize, SMEM_BYTES);

    // prep: pre-round doc and W to tf32 (removes in-loop B cvts everywhere)
    k_cvt<<<((size_t)B_ * D_ * H_) / 4 / 256, 256>>>(doc, p_doc);
    k_cvt<<<((size_t)H_ * H_) / 4 / 256, 256>>>(W, p_W);

    const float scale = 1.0f / 32.0f;   // 1/sqrt(H)

    // 1) q = query @ W + bias  (M=4096, N=1024, K=1024); B = g_W [K,N] NN
    {
        dim3 g(H_ / TN_, (B_ * Q_) / TM_, 1);
        wgemm<false, true, true, true><<<g, 256, SMEM_BYTES>>>(
            query, p_W, p_q, bias, H_, H_, H_, H_, 1.0f, 0, 0, 0);
    }
    // 2) scores = q @ doc^T * scale -> attn; B = g_doc [N,K] NT
    {
        dim3 g(D_ / TN_, Q_ / TM_, B_);
        wgemm<true, false, false, false><<<g, 256, SMEM_BYTES>>>(
            p_q, p_doc, attn, nullptr, H_, H_, H_, D_, scale,
            (size_t)Q_ * H_, (size_t)D_ * H_, (size_t)Q_ * D_);
    }
    // 3) masked softmax in place over D
    softmax_kernel<<<B_ * Q_, 256>>>(attn, mask);
    // 4) retrieved = attn @ doc; B = g_doc [K,N] NN, K = D
    {
        dim3 g(H_ / TN_, Q_ / TM_, B_);
        wgemm<false, false, true, false><<<g, 256, SMEM_BYTES>>>(
            attn, p_doc, retrieved, nullptr, D_, D_, H_, H_, 1.0f,
            (size_t)Q_ * D_, (size_t)D_ * H_, (size_t)Q_ * H_);
    }
}

// round 6
// speedup vs baseline: 1.0778x; 1.0778x over previous
#include <cuda_runtime.h>
#include <math.h>
#include <stdint.h>

#define B_  8
#define Q_  512
#define D_  4096
#define H_  1024

#define STAGES  3
#define TILE    128
#define BK      32
#define STRD    36                        // K-major smem row stride (floats)
#define STRD_BN 132                       // NN B smem row stride (floats)
#define A_FLOATS (TILE * STRD)            // 4608
#define B_FLOATS (TILE * STRD)            // 4608 (NN needs 32*132=4224 <= this)
#define STAGE_FLOATS (A_FLOATS + B_FLOATS)      // 9216
#define SMEM_BYTES (STAGES * STAGE_FLOATS * 4)  // 110592

// ---------------- scratch (static device memory; no allocs allowed) ----------
__device__ float g_q[(size_t)B_ * Q_ * H_];       // projected queries, tf32
__device__ float g_doc[(size_t)B_ * D_ * H_];     // tf32(doc)
__device__ float g_W[(size_t)H_ * H_];            // tf32(W)

// ---------------- helpers -----------------------------------------------------
__device__ __forceinline__ float tf32_rn(float x) {
    float r; asm("cvt.rna.tf32.f32 %0, %1;" : "=f"(r) : "f"(x)); return r;
}
__device__ __forceinline__ uint32_t tf32u(float x) {
    float r; asm("cvt.rna.tf32.f32 %0, %1;" : "=f"(r) : "f"(x));
    return __float_as_uint(r);
}
__device__ __forceinline__ void cp_async16(uint32_t dst, const void* src) {
    asm volatile("cp.async.cg.shared.global [%0], [%1], 16;" :: "r"(dst), "l"(src));
}
#define CP_COMMIT() asm volatile("cp.async.commit_group;" ::: "memory")
#define CP_WAIT(n)  asm volatile("cp.async.wait_group %0;" :: "n"(n) : "memory")

__device__ __forceinline__ uint32_t smem_u32(const void* p) {
    uint32_t a;
    asm("{ .reg .u64 t; cvta.to.shared.u64 t, %1; cvt.u32.u64 %0, t; }" : "=r"(a) : "l"(p));
    return a;
}

__device__ __forceinline__ void mma_tf32(float* c, const uint32_t* a, const uint32_t* b) {
    asm volatile(
        "mma.sync.aligned.m16n8k8.row.col.f32.tf32.tf32.f32 "
        "{%0,%1,%2,%3}, {%4,%5,%6,%7}, {%8,%9}, {%0,%1,%2,%3};"
        : "+f"(c[0]), "+f"(c[1]), "+f"(c[2]), "+f"(c[3])
        : "r"(a[0]), "r"(a[1]), "r"(a[2]), "r"(a[3]), "r"(b[0]), "r"(b[1]));
}

// ---------------- warp-MMA TF32 GEMM (CTA 128x128, warp 32x64, BK=32) ---------
// C[m][n] = alpha * sum_k A[m][k] * op(B) (+ bias[n])
//   A: [M,K] K-major, pitch lda (fp32; CVT_A => round in-register)
//   B_KMAJOR=1: B is [N,K] K-major rows, pitch ldb (pre-rounded tf32)
//   B_KMAJOR=0: B is [K,N], pitch ldb (pre-rounded tf32)
// grid: (N/128, M/128, batches), 256 threads, 2 CTAs/SM.
template <bool B_KMAJOR, bool HAS_BIAS, bool CVT_A, bool CVT_OUT>
__global__ void __launch_bounds__(256, 2) wgemm(
    const float* __restrict__ A, const float* __restrict__ Bm,
    float* __restrict__ C, const float* __restrict__ bias,
    int K, int lda, int ldb, int ldc, float alpha,
    size_t strideA, size_t strideB, size_t strideC)
{
    extern __shared__ float smf[];
    const uint32_t sbase = smem_u32(smf);

    const int tid  = threadIdx.x;
    const int lane = tid & 31;
    const int wid  = tid >> 5;
    const int row  = lane >> 2;          // 0..7
    const int tig  = lane & 3;           // 0..3
    const int warp_m = (wid & 3) * 32;   // 4 warps in M
    const int warp_n = (wid >> 2) * 64;  // 2 warps in N

    const size_t batch = blockIdx.z;
    const float* Ab = A + batch * strideA + (size_t)(blockIdx.y * TILE) * lda;
    const float* Bb;
    if (B_KMAJOR)
        Bb = Bm + batch * strideB + (size_t)(blockIdx.x * TILE) * ldb;
    else
        Bb = Bm + batch * strideB + blockIdx.x * TILE;

    float acc[2][8][4];
#pragma unroll
    for (int mt = 0; mt < 2; mt++)
#pragma unroll
        for (int nt = 0; nt < 8; nt++)
#pragma unroll
            for (int i = 0; i < 4; i++) acc[mt][nt][i] = 0.0f;

    const int NK = K / BK;

    auto load_stage = [&](int kb) {
        const int s = kb % STAGES;
        const uint32_t stA = sbase + s * STAGE_FLOATS * 4;
        const uint32_t stB = stA + A_FLOATS * 4;
        const float* gA = Ab + kb * BK;
#pragma unroll
        for (int r = 0; r < 4; r++) {
            const int c = tid + r * 256;          // 0..1023
            const int ar = c >> 3, aq = (c & 7) * 4;
            cp_async16(stA + (ar * STRD + aq) * 4, gA + (size_t)ar * lda + aq);
        }
        if (B_KMAJOR) {
            const float* gB = Bb + kb * BK;
#pragma unroll
            for (int r = 0; r < 4; r++) {
                const int c = tid + r * 256;
                const int br = c >> 3, bq = (c & 7) * 4;
                cp_async16(stB + (br * STRD + bq) * 4, gB + (size_t)br * ldb + bq);
            }
        } else {
            const float* gB = Bb + (size_t)(kb * BK) * ldb;
#pragma unroll
            for (int r = 0; r < 4; r++) {
                const int c = tid + r * 256;      // 0..1023
                const int bk = c >> 5, bn = (c & 31) * 4;
                cp_async16(stB + (bk * STRD_BN + bn) * 4, gB + (size_t)bk * ldb + bn);
            }
        }
    };

#pragma unroll
    for (int s = 0; s < STAGES - 1; s++) {
        load_stage(s);
        CP_COMMIT();
    }

    for (int kb = 0; kb < NK; kb++) {
        CP_WAIT(STAGES - 2);
        __syncthreads();

        const int kn = kb + STAGES - 1;
        if (kn < NK) load_stage(kn);
        CP_COMMIT();

        const float* As = smf + (kb % STAGES) * STAGE_FLOATS;
        const float* Bs = As + A_FLOATS;
#pragma unroll
        for (int kk = 0; kk < BK; kk += 8) {
            uint32_t a[2][4], b[8][2];
#pragma unroll
            for (int mt = 0; mt < 2; mt++) {
                const float* ap = As + (warp_m + mt * 16 + row) * STRD + kk + tig;
                if (CVT_A) {
                    a[mt][0] = tf32u(ap[0]);
                    a[mt][1] = tf32u(ap[8 * STRD]);
                    a[mt][2] = tf32u(ap[4]);
                    a[mt][3] = tf32u(ap[8 * STRD + 4]);
                } else {
                    a[mt][0] = __float_as_uint(ap[0]);
                    a[mt][1] = __float_as_uint(ap[8 * STRD]);
                    a[mt][2] = __float_as_uint(ap[4]);
                    a[mt][3] = __float_as_uint(ap[8 * STRD + 4]);
                }
            }
#pragma unroll
            for (int nt = 0; nt < 8; nt++) {
                if (B_KMAJOR) {
                    const float* bp = Bs + (warp_n + nt * 8 + row) * STRD + kk + tig;
                    b[nt][0] = __float_as_uint(bp[0]);
                    b[nt][1] = __float_as_uint(bp[4]);
                } else {
                    const float* bp = Bs + (size_t)(kk + tig) * STRD_BN + warp_n + nt * 8 + row;
                    b[nt][0] = __float_as_uint(bp[0]);
                    b[nt][1] = __float_as_uint(bp[4 * STRD_BN]);
                }
            }
#pragma unroll
            for (int mt = 0; mt < 2; mt++)
#pragma unroll
                for (int nt = 0; nt < 8; nt++)
                    mma_tf32(acc[mt][nt], a[mt], b[nt]);
        }
        __syncthreads();
    }

    // ---- epilogue ----
    float* Cb = C + batch * strideC;
#pragma unroll
    for (int mt = 0; mt < 2; mt++) {
        const int r0 = blockIdx.y * TILE + warp_m + mt * 16 + row;
#pragma unroll
        for (int nt = 0; nt < 8; nt++) {
            const int col = blockIdx.x * TILE + warp_n + nt * 8 + 2 * tig;
            float bx = 0.f, by = 0.f;
            if (HAS_BIAS) { bx = __ldg(bias + col); by = __ldg(bias + col + 1); }
            float2 v0, v1;
            v0.x = acc[mt][nt][0] * alpha + bx;
            v0.y = acc[mt][nt][1] * alpha + by;
            v1.x = acc[mt][nt][2] * alpha + bx;
            v1.y = acc[mt][nt][3] * alpha + by;
            if (CVT_OUT) {
                v0.x = tf32_rn(v0.x); v0.y = tf32_rn(v0.y);
                v1.x = tf32_rn(v1.x); v1.y = tf32_rn(v1.y);
            }
            *(float2*)(Cb + (size_t)r0 * ldc + col) = v0;
            *(float2*)(Cb + (size_t)(r0 + 8) * ldc + col) = v1;
        }
    }
}

// ---------------- elementwise tf32 round copy ---------------------------------
__global__ void k_cvt(const float* __restrict__ src, float* __restrict__ dst) {
    size_t i = (size_t)blockIdx.x * blockDim.x + threadIdx.x;
    float4 v = ((const float4*)src)[i];
    v.x = tf32_rn(v.x); v.y = tf32_rn(v.y); v.z = tf32_rn(v.z); v.w = tf32_rn(v.w);
    ((float4*)dst)[i] = v;
}

// ---------------- masked softmax over D (in place) ----------------------------
__global__ void __launch_bounds__(256) softmax_kernel(
    float* __restrict__ attn, const int* __restrict__ mask)
{
    const int row = blockIdx.x;            // b*Q_ + q
    const int b = row / Q_;
    const int* mrow = mask + (size_t)b * D_;
    float* s = attn + (size_t)row * D_;
    const int tid = threadIdx.x;

    float v[16];
    int mk[16];
    float mx = -INFINITY;
#pragma unroll
    for (int i = 0; i < 16; i++) {
        int d = tid + i * 256;
        mk[i] = mrow[d];
        float x = s[d];
        v[i] = (mk[i] != 0) ? x : -INFINITY;
        mx = fmaxf(mx, v[i]);
    }

    __shared__ float red[8];
#pragma unroll
    for (int off = 16; off > 0; off >>= 1)
        mx = fmaxf(mx, __shfl_xor_sync(0xffffffffu, mx, off));
    if ((tid & 31) == 0) red[tid >> 5] = mx;
    __syncthreads();
    if (tid < 32) {
        float m2 = (tid < 8) ? red[tid] : -INFINITY;
#pragma unroll
        for (int off = 4; off > 0; off >>= 1)
            m2 = fmaxf(m2, __shfl_xor_sync(0xffffffffu, m2, off));
        if (tid == 0) red[0] = m2;
    }
    __syncthreads();
    mx = red[0];

    float sum = 0.0f;
#pragma unroll
    for (int i = 0; i < 16; i++) {
        float e = (mk[i] != 0) ? expf(v[i] - mx) : 0.0f;
        v[i] = e;
        sum += e;
    }
#pragma unroll
    for (int off = 16; off > 0; off >>= 1)
        sum += __shfl_xor_sync(0xffffffffu, sum, off);
    __syncthreads();
    if ((tid & 31) == 0) red[tid >> 5] = sum;
    __syncthreads();
    if (tid < 32) {
        float s2 = (tid < 8) ? red[tid] : 0.0f;
#pragma unroll
        for (int off = 4; off > 0; off >>= 1)
            s2 += __shfl_xor_sync(0xffffffffu, s2, off);
        if (tid == 0) red[0] = s2;
    }
    __syncthreads();
    const float inv = 1.0f / red[0];

#pragma unroll
    for (int i = 0; i < 16; i++) {
        int d = tid + i * 256;
        s[d] = v[i] * inv;
    }
}

// ---------------- launch --------------------------------------------------------
extern "C" void kernel_launch(void* const* d_in, const int* in_sizes, int n_in,
                              void* d_out, int out_size)
{
    const float* query = (const float*)d_in[0];   // [B,Q,H]
    const float* doc   = (const float*)d_in[1];   // [B,D,H]
    const int*   mask  = (const int*)d_in[2];     // [B,D]
    const float* W     = (const float*)d_in[3];   // [H,H]
    const float* bias  = (const float*)d_in[4];   // [H]

    float* out = (float*)d_out;
    float* retrieved = out;                               // [B,Q,H]
    float* attn = out + (size_t)B_ * Q_ * H_;             // [B,Q,D]

    float *p_q, *p_doc, *p_W;
    cudaGetSymbolAddress((void**)&p_q, g_q);
    cudaGetSymbolAddress((void**)&p_doc, g_doc);
    cudaGetSymbolAddress((void**)&p_W, g_W);

    cudaFuncSetAttribute(wgemm<false, true, true, true>,
                         cudaFuncAttributeMaxDynamicSharedMemorySize, SMEM_BYTES);
    cudaFuncSetAttribute(wgemm<true, false, false, false>,
                         cudaFuncAttributeMaxDynamicSharedMemorySize, SMEM_BYTES);
    cudaFuncSetAttribute(wgemm<false, false, true, false>,
                         cudaFuncAttributeMaxDynamicSharedMemorySize, SMEM_BYTES);

    // prep: pre-round doc and W to tf32
    k_cvt<<<((size_t)B_ * D_ * H_) / 4 / 256, 256>>>(doc, p_doc);
    k_cvt<<<((size_t)H_ * H_) / 4 / 256, 256>>>(W, p_W);

    const float scale = 1.0f / 32.0f;   // 1/sqrt(H)

    // 1) q = query @ W + bias  (M=4096, N=1024, K=1024); B = g_W [K,N] NN
    {
        dim3 g(H_ / TILE, (B_ * Q_) / TILE, 1);
        wgemm<false, true, true, true><<<g, 256, SMEM_BYTES>>>(
            query, p_W, p_q, bias, H_, H_, H_, H_, 1.0f, 0, 0, 0);
    }
    // 2) scores = q @ doc^T * scale -> attn; B = g_doc [N,K] NT (no CVTs at all)
    {
        dim3 g(D_ / TILE, Q_ / TILE, B_);
        wgemm<true, false, false, false><<<g, 256, SMEM_BYTES>>>(
            p_q, p_doc, attn, nullptr, H_, H_, H_, D_, scale,
            (size_t)Q_ * H_, (size_t)D_ * H_, (size_t)Q_ * D_);
    }
    // 3) masked softmax in place over D
    softmax_kernel<<<B_ * Q_, 256>>>(attn, mask);
    // 4) retrieved = attn @ doc; B = g_doc [K,N] NN, K = D
    {
        dim3 g(H_ / TILE, Q_ / TILE, B_);
        wgemm<false, false, true, false><<<g, 256, SMEM_BYTES>>>(
            attn, p_doc, retrieved, nullptr, D_, D_, H_, H_, 1.0f,
            (size_t)Q_ * D_, (size_t)D_ * H_, (size_t)Q_ * H_);
    }
}

// round 7
// speedup vs baseline: 1.1546x; 1.0712x over previous
#include <cuda_runtime.h>
#include <math.h>
#include <stdint.h>

#define B_  8
#define Q_  512
#define D_  4096
#define H_  1024

#define STAGES  3
#define TILE    128
#define BK      32
#define STRD    36                        // K-major smem row stride (floats)
#define STRD_BN 136                       // NN B smem row stride (floats; mod 32 == 8 -> conflict-free)
#define A_FLOATS (TILE * STRD)            // 4608
#define B_FLOATS (TILE * STRD)            // 4608 (NN needs 32*136=4352 <= this)
#define STAGE_FLOATS (A_FLOATS + B_FLOATS)      // 9216
#define SMEM_BYTES (STAGES * STAGE_FLOATS * 4)  // 110592

// ---------------- scratch (static device memory; no allocs allowed) ----------
__device__ float g_q[(size_t)B_ * Q_ * H_];       // projected queries, tf32
__device__ float g_doc[(size_t)B_ * D_ * H_];     // tf32(doc)
__device__ float g_W[(size_t)H_ * H_];            // tf32(W)

// ---------------- helpers -----------------------------------------------------
__device__ __forceinline__ float tf32_rn(float x) {
    float r; asm("cvt.rna.tf32.f32 %0, %1;" : "=f"(r) : "f"(x)); return r;
}
__device__ __forceinline__ uint32_t tf32u(float x) {
    float r; asm("cvt.rna.tf32.f32 %0, %1;" : "=f"(r) : "f"(x));
    return __float_as_uint(r);
}
__device__ __forceinline__ void cp_async16(uint32_t dst, const void* src) {
    asm volatile("cp.async.cg.shared.global [%0], [%1], 16;" :: "r"(dst), "l"(src));
}
#define CP_COMMIT() asm volatile("cp.async.commit_group;" ::: "memory")
#define CP_WAIT(n)  asm volatile("cp.async.wait_group %0;" :: "n"(n) : "memory")

__device__ __forceinline__ uint32_t smem_u32(const void* p) {
    uint32_t a;
    asm("{ .reg .u64 t; cvta.to.shared.u64 t, %1; cvt.u32.u64 %0, t; }" : "=r"(a) : "l"(p));
    return a;
}

__device__ __forceinline__ void mma_tf32(float* c, const uint32_t* a, const uint32_t* b) {
    asm volatile(
        "mma.sync.aligned.m16n8k8.row.col.f32.tf32.tf32.f32 "
        "{%0,%1,%2,%3}, {%4,%5,%6,%7}, {%8,%9}, {%0,%1,%2,%3};"
        : "+f"(c[0]), "+f"(c[1]), "+f"(c[2]), "+f"(c[3])
        : "r"(a[0]), "r"(a[1]), "r"(a[2]), "r"(a[3]), "r"(b[0]), "r"(b[1]));
}

// ---------------- warp-MMA TF32 GEMM (CTA 128x128, warp 32x64, BK=32) ---------
// C[m][n] = alpha * sum_k A[m][k] * op(B) (+ bias[n])
//   A: [M,K] K-major, pitch lda (fp32; CVT_A => round in-register)
//   B_KMAJOR=1: B is [N,K] K-major rows, pitch ldb (pre-rounded tf32)
//   B_KMAJOR=0: B is [K,N], pitch ldb (pre-rounded tf32)
// grid: (N/128, M/128, batches), 256 threads, 2 CTAs/SM.
template <bool B_KMAJOR, bool HAS_BIAS, bool CVT_A, bool CVT_OUT>
__global__ void __launch_bounds__(256, 2) wgemm(
    const float* __restrict__ A, const float* __restrict__ Bm,
    float* __restrict__ C, const float* __restrict__ bias,
    int K, int lda, int ldb, int ldc, float alpha,
    size_t strideA, size_t strideB, size_t strideC)
{
    extern __shared__ float smf[];
    const uint32_t sbase = smem_u32(smf);

    const int tid  = threadIdx.x;
    const int lane = tid & 31;
    const int wid  = tid >> 5;
    const int row  = lane >> 2;          // 0..7
    const int tig  = lane & 3;           // 0..3
    const int warp_m = (wid & 3) * 32;   // 4 warps in M
    const int warp_n = (wid >> 2) * 64;  // 2 warps in N

    const size_t batch = blockIdx.z;
    const float* Ab = A + batch * strideA + (size_t)(blockIdx.y * TILE) * lda;
    const float* Bb;
    if (B_KMAJOR)
        Bb = Bm + batch * strideB + (size_t)(blockIdx.x * TILE) * ldb;
    else
        Bb = Bm + batch * strideB + blockIdx.x * TILE;

    float acc[2][8][4];
#pragma unroll
    for (int mt = 0; mt < 2; mt++)
#pragma unroll
        for (int nt = 0; nt < 8; nt++)
#pragma unroll
            for (int i = 0; i < 4; i++) acc[mt][nt][i] = 0.0f;

    const int NK = K / BK;

    auto load_stage = [&](int kb) {
        const int s = kb % STAGES;
        const uint32_t stA = sbase + s * STAGE_FLOATS * 4;
        const uint32_t stB = stA + A_FLOATS * 4;
        const float* gA = Ab + kb * BK;
#pragma unroll
        for (int r = 0; r < 4; r++) {
            const int c = tid + r * 256;          // 0..1023
            const int ar = c >> 3, aq = (c & 7) * 4;
            cp_async16(stA + (ar * STRD + aq) * 4, gA + (size_t)ar * lda + aq);
        }
        if (B_KMAJOR) {
            const float* gB = Bb + kb * BK;
#pragma unroll
            for (int r = 0; r < 4; r++) {
                const int c = tid + r * 256;
                const int br = c >> 3, bq = (c & 7) * 4;
                cp_async16(stB + (br * STRD + bq) * 4, gB + (size_t)br * ldb + bq);
            }
        } else {
            const float* gB = Bb + (size_t)(kb * BK) * ldb;
#pragma unroll
            for (int r = 0; r < 4; r++) {
                const int c = tid + r * 256;      // 0..1023
                const int bk = c >> 5, bn = (c & 31) * 4;
                cp_async16(stB + (bk * STRD_BN + bn) * 4, gB + (size_t)bk * ldb + bn);
            }
        }
    };

#pragma unroll
    for (int s = 0; s < STAGES - 1; s++) {
        load_stage(s);
        CP_COMMIT();
    }

    for (int kb = 0; kb < NK; kb++) {
        CP_WAIT(STAGES - 2);
        __syncthreads();

        const int kn = kb + STAGES - 1;
        if (kn < NK) load_stage(kn);
        CP_COMMIT();

        const float* As = smf + (kb % STAGES) * STAGE_FLOATS;
        const float* Bs = As + A_FLOATS;
#pragma unroll
        for (int kk = 0; kk < BK; kk += 8) {
            uint32_t a[2][4], b[8][2];
#pragma unroll
            for (int mt = 0; mt < 2; mt++) {
                const float* ap = As + (warp_m + mt * 16 + row) * STRD + kk + tig;
                if (CVT_A) {
                    a[mt][0] = tf32u(ap[0]);
                    a[mt][1] = tf32u(ap[8 * STRD]);
                    a[mt][2] = tf32u(ap[4]);
                    a[mt][3] = tf32u(ap[8 * STRD + 4]);
                } else {
                    a[mt][0] = __float_as_uint(ap[0]);
                    a[mt][1] = __float_as_uint(ap[8 * STRD]);
                    a[mt][2] = __float_as_uint(ap[4]);
                    a[mt][3] = __float_as_uint(ap[8 * STRD + 4]);
                }
            }
#pragma unroll
            for (int nt = 0; nt < 8; nt++) {
                if (B_KMAJOR) {
                    const float* bp = Bs + (warp_n + nt * 8 + row) * STRD + kk + tig;
                    b[nt][0] = __float_as_uint(bp[0]);
                    b[nt][1] = __float_as_uint(bp[4]);
                } else {
                    const float* bp = Bs + (size_t)(kk + tig) * STRD_BN + warp_n + nt * 8 + row;
                    b[nt][0] = __float_as_uint(bp[0]);
                    b[nt][1] = __float_as_uint(bp[4 * STRD_BN]);
                }
            }
#pragma unroll
            for (int mt = 0; mt < 2; mt++)
#pragma unroll
                for (int nt = 0; nt < 8; nt++)
                    mma_tf32(acc[mt][nt], a[mt], b[nt]);
        }
        __syncthreads();
    }

    // ---- epilogue ----
    float* Cb = C + batch * strideC;
#pragma unroll
    for (int mt = 0; mt < 2; mt++) {
        const int r0 = blockIdx.y * TILE + warp_m + mt * 16 + row;
#pragma unroll
        for (int nt = 0; nt < 8; nt++) {
            const int col = blockIdx.x * TILE + warp_n + nt * 8 + 2 * tig;
            float bx = 0.f, by = 0.f;
            if (HAS_BIAS) { bx = __ldg(bias + col); by = __ldg(bias + col + 1); }
            float2 v0, v1;
            v0.x = acc[mt][nt][0] * alpha + bx;
            v0.y = acc[mt][nt][1] * alpha + by;
            v1.x = acc[mt][nt][2] * alpha + bx;
            v1.y = acc[mt][nt][3] * alpha + by;
            if (CVT_OUT) {
                v0.x = tf32_rn(v0.x); v0.y = tf32_rn(v0.y);
                v1.x = tf32_rn(v1.x); v1.y = tf32_rn(v1.y);
            }
            *(float2*)(Cb + (size_t)r0 * ldc + col) = v0;
            *(float2*)(Cb + (size_t)(r0 + 8) * ldc + col) = v1;
        }
    }
}

// ---------------- elementwise tf32 round copy ---------------------------------
__global__ void k_cvt(const float* __restrict__ src, float* __restrict__ dst) {
    size_t i = (size_t)blockIdx.x * blockDim.x + threadIdx.x;
    float4 v = ((const float4*)src)[i];
    v.x = tf32_rn(v.x); v.y = tf32_rn(v.y); v.z = tf32_rn(v.z); v.w = tf32_rn(v.w);
    ((float4*)dst)[i] = v;
}

// ---------------- masked softmax over D (in place, tf32-rounded output) -------
__global__ void __launch_bounds__(256) softmax_kernel(
    float* __restrict__ attn, const int* __restrict__ mask)
{
    const int row = blockIdx.x;            // b*Q_ + q
    const int b = row / Q_;
    const int4* mrow = (const int4*)(mask + (size_t)b * D_);
    float4* s4 = (float4*)(attn + (size_t)row * D_);
    const int tid = threadIdx.x;

    float v[16];
    float mx = -INFINITY;
#pragma unroll
    for (int i = 0; i < 4; i++) {
        const int c = tid + i * 256;
        int4 m = mrow[c];
        float4 x = s4[c];
        v[i * 4 + 0] = (m.x != 0) ? x.x : -INFINITY;
        v[i * 4 + 1] = (m.y != 0) ? x.y : -INFINITY;
        v[i * 4 + 2] = (m.z != 0) ? x.z : -INFINITY;
        v[i * 4 + 3] = (m.w != 0) ? x.w : -INFINITY;
        mx = fmaxf(mx, fmaxf(fmaxf(v[i * 4], v[i * 4 + 1]), fmaxf(v[i * 4 + 2], v[i * 4 + 3])));
    }

    __shared__ float red[8];
#pragma unroll
    for (int off = 16; off > 0; off >>= 1)
        mx = fmaxf(mx, __shfl_xor_sync(0xffffffffu, mx, off));
    if ((tid & 31) == 0) red[tid >> 5] = mx;
    __syncthreads();
    if (tid < 32) {
        float m2 = (tid < 8) ? red[tid] : -INFINITY;
#pragma unroll
        for (int off = 4; off > 0; off >>= 1)
            m2 = fmaxf(m2, __shfl_xor_sync(0xffffffffu, m2, off));
        if (tid == 0) red[0] = m2;
    }
    __syncthreads();
    mx = red[0];

    float sum = 0.0f;
#pragma unroll
    for (int i = 0; i < 16; i++) {
        float e = (v[i] != -INFINITY) ? expf(v[i] - mx) : 0.0f;
        v[i] = e;
        sum += e;
    }
#pragma unroll
    for (int off = 16; off > 0; off >>= 1)
        sum += __shfl_xor_sync(0xffffffffu, sum, off);
    __syncthreads();
    if ((tid & 31) == 0) red[tid >> 5] = sum;
    __syncthreads();
    if (tid < 32) {
        float s2 = (tid < 8) ? red[tid] : 0.0f;
#pragma unroll
        for (int off = 4; off > 0; off >>= 1)
            s2 += __shfl_xor_sync(0xffffffffu, s2, off);
        if (tid == 0) red[0] = s2;
    }
    __syncthreads();
    const float inv = 1.0f / red[0];

    // write tf32-rounded weights: they are both the kernel output and GEMM3's A
#pragma unroll
    for (int i = 0; i < 4; i++) {
        float4 o;
        o.x = tf32_rn(v[i * 4 + 0] * inv);
        o.y = tf32_rn(v[i * 4 + 1] * inv);
        o.z = tf32_rn(v[i * 4 + 2] * inv);
        o.w = tf32_rn(v[i * 4 + 3] * inv);
        s4[tid + i * 256] = o;
    }
}

// ---------------- launch --------------------------------------------------------
extern "C" void kernel_launch(void* const* d_in, const int* in_sizes, int n_in,
                              void* d_out, int out_size)
{
    const float* query = (const float*)d_in[0];   // [B,Q,H]
    const float* doc   = (const float*)d_in[1];   // [B,D,H]
    const int*   mask  = (const int*)d_in[2];     // [B,D]
    const float* W     = (const float*)d_in[3];   // [H,H]
    const float* bias  = (const float*)d_in[4];   // [H]

    float* out = (float*)d_out;
    float* retrieved = out;                               // [B,Q,H]
    float* attn = out + (size_t)B_ * Q_ * H_;             // [B,Q,D]

    float *p_q, *p_doc, *p_W;
    cudaGetSymbolAddress((void**)&p_q, g_q);
    cudaGetSymbolAddress((void**)&p_doc, g_doc);
    cudaGetSymbolAddress((void**)&p_W, g_W);

    cudaFuncSetAttribute(wgemm<false, true, true, true>,
                         cudaFuncAttributeMaxDynamicSharedMemorySize, SMEM_BYTES);
    cudaFuncSetAttribute(wgemm<true, false, false, false>,
                         cudaFuncAttributeMaxDynamicSharedMemorySize, SMEM_BYTES);
    cudaFuncSetAttribute(wgemm<false, false, false, false>,
                         cudaFuncAttributeMaxDynamicSharedMemorySize, SMEM_BYTES);

    // prep: pre-round doc and W to tf32
    k_cvt<<<((size_t)B_ * D_ * H_) / 4 / 256, 256>>>(doc, p_doc);
    k_cvt<<<((size_t)H_ * H_) / 4 / 256, 256>>>(W, p_W);

    const float scale = 1.0f / 32.0f;   // 1/sqrt(H)

    // 1) q = query @ W + bias  (M=4096, N=1024, K=1024); B = g_W [K,N] NN
    {
        dim3 g(H_ / TILE, (B_ * Q_) / TILE, 1);
        wgemm<false, true, true, true><<<g, 256, SMEM_BYTES>>>(
            query, p_W, p_q, bias, H_, H_, H_, H_, 1.0f, 0, 0, 0);
    }
    // 2) scores = q @ doc^T * scale -> attn; B = g_doc [N,K] NT (no CVTs at all)
    {
        dim3 g(D_ / TILE, Q_ / TILE, B_);
        wgemm<true, false, false, false><<<g, 256, SMEM_BYTES>>>(
            p_q, p_doc, attn, nullptr, H_, H_, H_, D_, scale,
            (size_t)Q_ * H_, (size_t)D_ * H_, (size_t)Q_ * D_);
    }
    // 3) masked softmax in place over D (emits tf32-rounded weights)
    softmax_kernel<<<B_ * Q_, 256>>>(attn, mask);
    // 4) retrieved = attn @ doc; B = g_doc [K,N] NN, K = D (no CVTs at all)
    {
        dim3 g(H_ / TILE, Q_ / TILE, B_);
        wgemm<false, false, false, false><<<g, 256, SMEM_BYTES>>>(
            attn, p_doc, retrieved, nullptr, D_, D_, H_, H_, 1.0f,
            (size_t)Q_ * D_, (size_t)D_ * H_, (size_t)Q_ * H_);
    }
}